// round 6
// baseline (speedup 1.0000x reference)
#include <cuda_runtime.h>

#define T_LEN 2048
#define HID   15
#define EDIM  300
#define G4    60            // 4*HID gates
#define TPAD  (T_LEN + 4)   // pad so prefetch never needs a branch

// Precomputed input-projection gates (PRE-SCALED per gate row), [2][TPAD][G4]
__device__ float g_pre[2 * TPAD * G4];

// ---------------------------------------------------------------------------
// Kernel 1: pre[s][t][j] = scale_j * (b_ih[j] + b_hh[j] + emb[tok]·W_ih[j])
// scale_j = 0.5 for i/f/o rows (sigmoid via 0.5*tanh(0.5x)+0.5), 1.0 for g rows.
// ---------------------------------------------------------------------------
__global__ void precompute_kernel(const int* __restrict__ s1,
                                  const int* __restrict__ s2,
                                  const float* __restrict__ emb,
                                  const float* __restrict__ W_ih,
                                  const float* __restrict__ b_ih,
                                  const float* __restrict__ b_hh) {
    __shared__ float4 semb[EDIM / 4];

    const int bid = blockIdx.x;
    const int s   = bid >> 11;
    const int t   = bid & (T_LEN - 1);
    const int tok = (s == 0) ? s1[t] : s2[t];

    const float4* erow = reinterpret_cast<const float4*>(emb + (long long)tok * EDIM);
    for (int i = threadIdx.x; i < EDIM / 4; i += blockDim.x)
        semb[i] = erow[i];
    __syncthreads();

    const int j = threadIdx.x;
    if (j < G4) {
        const float4* wrow = reinterpret_cast<const float4*>(W_ih + j * EDIM);
        float a0 = 0.f, a1 = 0.f, a2 = 0.f, a3 = 0.f;
        #pragma unroll 5
        for (int e = 0; e < EDIM / 4; e++) {
            float4 wv = wrow[e];
            float4 xv = semb[e];
            a0 = fmaf(wv.x, xv.x, a0);
            a1 = fmaf(wv.y, xv.y, a1);
            a2 = fmaf(wv.z, xv.z, a2);
            a3 = fmaf(wv.w, xv.w, a3);
        }
        const float scale = (j >= 30 && j < 45) ? 1.0f : 0.5f;  // g rows: 1.0
        float acc = b_ih[j] + b_hh[j] + ((a0 + a1) + (a2 + a3));
        g_pre[(s * TPAD + t) * G4 + j] = scale * acc;
    }
}

// ---- packed f32x2 + MUFU helpers -----------------------------------------
__device__ __forceinline__ float tanhfast(float x) {
    float y; asm("tanh.approx.f32 %0, %1;" : "=f"(y) : "f"(x)); return y;
}
__device__ __forceinline__ unsigned long long pk(float lo, float hi) {
    unsigned long long r;
    asm("mov.b64 %0, {%1, %2};" : "=l"(r) : "f"(lo), "f"(hi)); return r;
}
__device__ __forceinline__ void upk(float& lo, float& hi, unsigned long long v) {
    asm("mov.b64 {%0, %1}, %2;" : "=f"(lo), "=f"(hi) : "l"(v));
}
__device__ __forceinline__ unsigned long long fma2(unsigned long long a,
                                                   unsigned long long b,
                                                   unsigned long long c) {
    unsigned long long d;
    asm("fma.rn.f32x2 %0, %1, %2, %3;" : "=l"(d) : "l"(a), "l"(b), "l"(c));
    return d;
}
__device__ __forceinline__ unsigned long long mul2(unsigned long long a,
                                                   unsigned long long b) {
    unsigned long long d;
    asm("mul.rn.f32x2 %0, %1, %2;" : "=l"(d) : "l"(a), "l"(b));
    return d;
}
__device__ __forceinline__ unsigned long long add2(unsigned long long a,
                                                   unsigned long long b) {
    unsigned long long d;
    asm("add.rn.f32x2 %0, %1, %2;" : "=l"(d) : "l"(a), "l"(b));
    return d;
}

// ---------------------------------------------------------------------------
// Kernel 2: both LSTM recurrences (1 warp each) + fused MLP.
// Lane k<15: gates i_k,g_k; holds h_k,c_k.  Lane 16+k: gates f_k,o_k.
// h broadcast: state lanes STS.64 packed (h,h); all lanes LDS.128 (broadcast).
// Packed f32x2 dots compute (aa,ab) simultaneously.
// ---------------------------------------------------------------------------
__global__ __launch_bounds__(64, 1)
void recurrence_kernel(const float* __restrict__ W_hh,
                       const float* __restrict__ W1,
                       const float* __restrict__ b1,
                       const float* __restrict__ W2,
                       const float* __restrict__ b2,
                       const float* __restrict__ h1_0,
                       const float* __restrict__ c1_0,
                       const float* __restrict__ h2_0,
                       const float* __restrict__ c2_0,
                       float* __restrict__ out) {
    const int tid  = threadIdx.x;
    const int w    = tid >> 5;
    const int lane = tid & 31;

    __shared__ __align__(16) unsigned long long shh[2][16];  // (h,h) pairs
    __shared__ float sh_h[2][16];
    __shared__ float sh_hidden[25];

    const bool lowhalf = (lane < 16);
    const int  sub     = lowhalf ? lane : lane - 16;
    const bool valid   = (sub < HID);

    const int ia = valid ? (lowhalf ? sub      : 15 + sub) : 0;  // i / f
    const int ib = valid ? (lowhalf ? 30 + sub : 45 + sub) : 0;  // g / o

    // Pre-scaled recurrent weight rows, packed (Wa,Wb) per k
    // row-a (i/f): sigmoid -> 0.5 ; row-b: g (low) 1.0, o (high) 0.5
    const float sB = lowhalf ? 1.0f : 0.5f;
    unsigned long long WW[HID];
    #pragma unroll
    for (int m = 0; m < HID; m++) {
        float wa = valid ? 0.5f * W_hh[ia * HID + m] : 0.0f;
        float wb = valid ? sB   * W_hh[ib * HID + m] : 0.0f;
        WW[m] = pk(wa, wb);
    }

    const float* baseA = g_pre + w * (TPAD * G4) + ia;
    const float* baseB = g_pre + w * (TPAD * G4) + ib;

    const float* h0p = (w == 0) ? h1_0 : h2_0;
    const float* c0p = (w == 0) ? c1_0 : c2_0;
    float cval = (lowhalf && valid) ? c0p[sub] : 0.0f;
    float hval = (lowhalf && valid) ? h0p[sub] : 0.0f;

    // init packed h smem (slot 15 zero pad)
    if (lowhalf) shh[w][lane] = pk(valid ? hval : 0.0f, valid ? hval : 0.0f);
    __syncthreads();

    // two-deep register prefetch of pre (pad absorbs overrun)
    float paC = baseA[0],  pbC = baseB[0];
    float paN = baseA[G4], pbN = baseB[G4];
    int   off = 2 * G4;

    const ulonglong2* q = reinterpret_cast<const ulonglong2*>(shh[w]);

    #pragma unroll 2
    for (int t = 0; t < T_LEN; t++) {
        const float pa = paC, pb = pbC;
        paC = paN; pbC = pbN;
        paN = __ldg(baseA + off);
        pbN = __ldg(baseB + off);
        off += G4;

        __syncwarp();
        // 8x LDS.128, each yields two (h,h) pairs; all-lane broadcast
        ulonglong2 q0 = q[0], q1 = q[1], q2 = q[2], q3 = q[3];
        ulonglong2 q4 = q[4], q5 = q[5], q6 = q[6], q7 = q[7];

        // packed dots: acc = (aa, ab), 4-way split over 15 pairs
        unsigned long long acc0 = fma2(WW[0], q0.x, pk(pa, pb));
        unsigned long long acc1 = mul2(WW[1], q0.y);
        unsigned long long acc2 = mul2(WW[2], q1.x);
        unsigned long long acc3 = mul2(WW[3], q1.y);
        acc0 = fma2(WW[4],  q2.x, acc0);
        acc1 = fma2(WW[5],  q2.y, acc1);
        acc2 = fma2(WW[6],  q3.x, acc2);
        acc3 = fma2(WW[7],  q3.y, acc3);
        acc0 = fma2(WW[8],  q4.x, acc0);
        acc1 = fma2(WW[9],  q4.y, acc1);
        acc2 = fma2(WW[10], q5.x, acc2);
        acc3 = fma2(WW[11], q5.y, acc3);
        acc0 = fma2(WW[12], q6.x, acc0);
        acc1 = fma2(WW[13], q6.y, acc1);
        acc2 = fma2(WW[14], q7.x, acc2);
        unsigned long long s = add2(add2(acc0, acc1), add2(acc2, acc3));
        float aa, ab; upk(aa, ab, s);

        // raw tanh of pre-scaled gates
        float ta = tanhfast(aa);   // i (low) / f (high), raw
        float tb = tanhfast(ab);   // g (low) / o (high), raw

        // local (low-lane) products overlap the shfl_down latency
        float iv = fmaf(0.5f, ta, 0.5f);   // i = sigmoid
        float ig = iv * tb;                // i * g   (g = tb on low lanes)

        float taf = __shfl_down_sync(0xffffffffu, ta, 16);  // raw f
        float tbo = __shfl_down_sync(0xffffffffu, tb, 16);  // raw o

        float fv = fmaf(0.5f, taf, 0.5f);
        cval = fmaf(fv, cval, ig);
        float ov = fmaf(0.5f, tbo, 0.5f);  // overlaps tanh(c) latency
        float tc = tanhfast(cval);
        hval = ov * tc;

        if (lane < HID) shh[w][lane] = pk(hval, hval);
    }

    // ---- fused final MLP ----
    if (lowhalf && valid) sh_h[w][sub] = hval;
    __syncthreads();

    if (tid < 25) {
        const float* w1r = W1 + tid * (5 * HID);
        float acc = b1[tid];
        #pragma unroll
        for (int kk = 0; kk < HID; kk++) {
            float v1 = sh_h[0][kk];
            float v2 = sh_h[1][kk];
            acc = fmaf(w1r[kk],           v1,               acc);
            acc = fmaf(w1r[HID + kk],     fabsf(v1 - v2),   acc);
            acc = fmaf(w1r[2 * HID + kk], v2,               acc);
            acc = fmaf(w1r[3 * HID + kk], v1 * v2,          acc);
            acc = fmaf(w1r[4 * HID + kk], 0.5f * (v1 + v2), acc);
        }
        sh_hidden[tid] = acc;
    }
    __syncthreads();

    if (tid < 2) {
        float acc = b2[tid];
        #pragma unroll
        for (int j = 0; j < 25; j++)
            acc = fmaf(W2[tid * 25 + j], sh_hidden[j], acc);
        out[tid] = acc;
    }
}

extern "C" void kernel_launch(void* const* d_in, const int* in_sizes, int n_in,
                              void* d_out, int out_size) {
    const int*   s1   = (const int*)  d_in[0];
    const int*   s2   = (const int*)  d_in[1];
    const float* emb  = (const float*)d_in[2];
    const float* W_ih = (const float*)d_in[3];
    const float* W_hh = (const float*)d_in[4];
    const float* b_ih = (const float*)d_in[5];
    const float* b_hh = (const float*)d_in[6];
    const float* W1   = (const float*)d_in[7];
    const float* b1   = (const float*)d_in[8];
    const float* W2   = (const float*)d_in[9];
    const float* b2   = (const float*)d_in[10];
    const float* h1_0 = (const float*)d_in[11];
    const float* c1_0 = (const float*)d_in[12];
    const float* h2_0 = (const float*)d_in[13];
    const float* c2_0 = (const float*)d_in[14];
    float* out = (float*)d_out;

    precompute_kernel<<<2 * T_LEN, 64>>>(s1, s2, emb, W_ih, b_ih, b_hh);
    recurrence_kernel<<<1, 64>>>(W_hh, W1, b1, W2, b2,
                                 h1_0, c1_0, h2_0, c2_0, out);
}